// round 1
// baseline (speedup 1.0000x reference)
#include <cuda_runtime.h>
#include <math.h>

// ---------------- problem constants ----------------
#define L        1024
#define DMODEL   1024
#define DINNER   2048
#define NH       32
#define HD       64
#define NSTATE   64
#define CONVDIM  2176           // DINNER + 2*G*N = 2048 + 128
#define DINPROJ  4256           // 2*DINNER + 2*G*N + NH
#define OFF_Z    0
#define OFF_XBC  2048
#define OFF_B    2048           // within xbc buffer: x [0,2048), B [2048,2112), C [2112,2176)
#define OFF_DT   4224
#define EPSF     1e-5f

// ---------------- scratch (device globals; no allocs allowed) ----------------
__device__ float g_zx_f[L * DINPROJ];
__device__ float g_zx_b[L * DINPROJ];
__device__ float g_xbc_f[L * CONVDIM];
__device__ float g_xbc_b[L * CONVDIM];
__device__ float g_dt_f[L * NH];
__device__ float g_dt_b[L * NH];
__device__ float g_dA_f[L * NH];
__device__ float g_dA_b[L * NH];
__device__ float g_y_f[L * DINNER];
__device__ float g_y_b[L * DINNER];
__device__ float g_o_f[L * DMODEL];
__device__ float g_o_b[L * DMODEL];

__device__ __forceinline__ float siluf(float x) { return x / (1.f + expf(-x)); }

// ---------------- SGEMM: C[M,N] = op(A)[M,K] * W[N,K]^T ----------------
// MODE 0: A plain row-major [M,K]
// MODE 1: A row-reversed (row m reads A[M-1-m])  (time flip for backward dir)
// MODE 2: A[m,k] = silu( k<DMODEL ? Af[m,k] : Ab[M-1-m, k-DMODEL] )  (final concat)
template <int MODE>
__global__ void __launch_bounds__(256) sgemm_nt(
    const float* __restrict__ A, const float* __restrict__ A2,
    const float* __restrict__ W, float* __restrict__ C,
    int M, int N, int K)
{
    __shared__ float sA[8][128];
    __shared__ float sW[8][128];

    const int tid = threadIdx.x;
    const int bm  = blockIdx.y * 128;
    const int bn  = blockIdx.x * 128;

    const int lrow = tid >> 1;        // 0..127
    const int lk   = (tid & 1) * 4;   // 0 or 4

    const int tx = tid & 15;          // 0..15
    const int ty = tid >> 4;          // 0..15

    float acc[8][8];
#pragma unroll
    for (int i = 0; i < 8; i++)
#pragma unroll
        for (int j = 0; j < 8; j++) acc[i][j] = 0.f;

    for (int k0 = 0; k0 < K; k0 += 8) {
        // ---- load A tile (128 x 8), transposed into sA[k][m] ----
        {
            const int gm = bm + lrow;
            float4 av;
            if (MODE == 0) {
                av = *reinterpret_cast<const float4*>(&A[(size_t)gm * K + k0 + lk]);
            } else if (MODE == 1) {
                av = *reinterpret_cast<const float4*>(&A[(size_t)(M - 1 - gm) * K + k0 + lk]);
            } else {
                const int kk = k0 + lk;
                if (kk < DMODEL)
                    av = *reinterpret_cast<const float4*>(&A[(size_t)gm * DMODEL + kk]);
                else
                    av = *reinterpret_cast<const float4*>(&A2[(size_t)(M - 1 - gm) * DMODEL + (kk - DMODEL)]);
                av.x = siluf(av.x); av.y = siluf(av.y); av.z = siluf(av.z); av.w = siluf(av.w);
            }
            sA[lk + 0][lrow] = av.x;
            sA[lk + 1][lrow] = av.y;
            sA[lk + 2][lrow] = av.z;
            sA[lk + 3][lrow] = av.w;
        }
        // ---- load W tile (128 x 8), transposed into sW[k][n], guarded in N ----
        {
            const int gn = bn + lrow;
            float4 wv = make_float4(0.f, 0.f, 0.f, 0.f);
            if (gn < N)
                wv = *reinterpret_cast<const float4*>(&W[(size_t)gn * K + k0 + lk]);
            sW[lk + 0][lrow] = wv.x;
            sW[lk + 1][lrow] = wv.y;
            sW[lk + 2][lrow] = wv.z;
            sW[lk + 3][lrow] = wv.w;
        }
        __syncthreads();

#pragma unroll
        for (int kk = 0; kk < 8; kk++) {
            float a[8], b[8];
            *reinterpret_cast<float4*>(a)     = *reinterpret_cast<const float4*>(&sA[kk][ty * 4]);
            *reinterpret_cast<float4*>(a + 4) = *reinterpret_cast<const float4*>(&sA[kk][64 + ty * 4]);
            *reinterpret_cast<float4*>(b)     = *reinterpret_cast<const float4*>(&sW[kk][tx * 4]);
            *reinterpret_cast<float4*>(b + 4) = *reinterpret_cast<const float4*>(&sW[kk][64 + tx * 4]);
#pragma unroll
            for (int i = 0; i < 8; i++)
#pragma unroll
                for (int j = 0; j < 8; j++)
                    acc[i][j] = fmaf(a[i], b[j], acc[i][j]);
        }
        __syncthreads();
    }

    // ---- writeback ----
#pragma unroll
    for (int i = 0; i < 8; i++) {
        const int m = bm + ((i < 4) ? (ty * 4 + i) : (64 + ty * 4 + i - 4));
#pragma unroll
        for (int j = 0; j < 8; j++) {
            const int n = bn + ((j < 4) ? (tx * 4 + j) : (64 + tx * 4 + j - 4));
            if (n < N) C[(size_t)m * N + n] = acc[i][j];
        }
    }
}

// ---------------- depthwise causal conv (width 4) + SiLU ----------------
__global__ void conv_silu_kernel(const float* __restrict__ zx,
                                 const float* __restrict__ cw,
                                 const float* __restrict__ cb,
                                 float* __restrict__ out)
{
    const int idx = blockIdx.x * blockDim.x + threadIdx.x;
    if (idx >= L * CONVDIM) return;
    const int t = idx / CONVDIM;
    const int c = idx - t * CONVDIM;
    float acc = cb[c];
#pragma unroll
    for (int k = 0; k < 4; k++) {
        const int tt = t - 3 + k;
        if (tt >= 0)
            acc = fmaf(zx[(size_t)tt * DINPROJ + OFF_XBC + c], cw[c * 4 + k], acc);
    }
    out[(size_t)t * CONVDIM + c] = siluf(acc);
}

// ---------------- dt softplus + dA ----------------
__global__ void dt_kernel(const float* __restrict__ zx,
                          const float* __restrict__ dt_bias,
                          const float* __restrict__ A_log,
                          float* __restrict__ dt_out,
                          float* __restrict__ dA_out)
{
    const int idx = blockIdx.x * blockDim.x + threadIdx.x;
    if (idx >= L * NH) return;
    const int h = idx & (NH - 1);
    const float v = zx[(size_t)(idx >> 5) * DINPROJ + OFF_DT + h] + dt_bias[h];
    const float sp = (v > 20.f) ? v : log1pf(expf(v));
    dt_out[idx] = sp;
    dA_out[idx] = expf(sp * (-expf(A_log[h])));
}

// ---------------- SSM scan ----------------
// grid: (2 psplit, 32 heads). 256 threads. Each thread owns 8 state elems:
// p_local = tid>>3 (32 rows), n0 = (tid&7)*8.
#define SCHUNK 16
__global__ void __launch_bounds__(256) scan_kernel(
    const float* __restrict__ xbc, const float* __restrict__ dt,
    const float* __restrict__ dA, const float* __restrict__ Dp,
    float* __restrict__ y)
{
    const int head = blockIdx.y;
    const int ps   = blockIdx.x;          // 0/1 -> p offset 0/32
    const int tid  = threadIdx.x;
    const int pl   = tid >> 3;            // 0..31
    const int n0   = (tid & 7) * 8;
    const float Dh = Dp[head];
    const int xoff = head * HD + ps * 32;

    __shared__ float sB[SCHUNK][64];
    __shared__ float sC[SCHUNK][64];
    __shared__ float sx[SCHUNK][32];
    __shared__ float sdt[SCHUNK];
    __shared__ float sdA[SCHUNK];

    float h[8];
#pragma unroll
    for (int j = 0; j < 8; j++) h[j] = 0.f;

    for (int t0 = 0; t0 < L; t0 += SCHUNK) {
        // cooperative stage: 16 timesteps of B, C, x(32 rows), dt, dA
        {
            const int lt = tid >> 4;            // 0..15
            const int lc = (tid & 15) * 4;      // 0..60
            const int t  = t0 + lt;
            *reinterpret_cast<float4*>(&sB[lt][lc]) =
                *reinterpret_cast<const float4*>(&xbc[(size_t)t * CONVDIM + OFF_B + lc]);
            *reinterpret_cast<float4*>(&sC[lt][lc]) =
                *reinterpret_cast<const float4*>(&xbc[(size_t)t * CONVDIM + OFF_B + 64 + lc]);
            if (lc < 32)
                *reinterpret_cast<float4*>(&sx[lt][lc]) =
                    *reinterpret_cast<const float4*>(&xbc[(size_t)t * CONVDIM + xoff + lc]);
            if (tid < SCHUNK) {
                sdt[tid] = dt[(size_t)(t0 + tid) * NH + head];
                sdA[tid] = dA[(size_t)(t0 + tid) * NH + head];
            }
        }
        __syncthreads();

        for (int tt = 0; tt < SCHUNK; tt++) {
            const float dtv = sdt[tt];
            const float dAv = sdA[tt];
            const float xp  = sx[tt][pl];
            const float dtx = dtv * xp;
            float b[8], c[8];
            *reinterpret_cast<float4*>(b)     = *reinterpret_cast<const float4*>(&sB[tt][n0]);
            *reinterpret_cast<float4*>(b + 4) = *reinterpret_cast<const float4*>(&sB[tt][n0 + 4]);
            *reinterpret_cast<float4*>(c)     = *reinterpret_cast<const float4*>(&sC[tt][n0]);
            *reinterpret_cast<float4*>(c + 4) = *reinterpret_cast<const float4*>(&sC[tt][n0 + 4]);
            float acc = 0.f;
#pragma unroll
            for (int j = 0; j < 8; j++) {
                h[j] = fmaf(h[j], dAv, dtx * b[j]);
                acc  = fmaf(h[j], c[j], acc);
            }
            acc += __shfl_down_sync(0xffffffffu, acc, 4, 8);
            acc += __shfl_down_sync(0xffffffffu, acc, 2, 8);
            acc += __shfl_down_sync(0xffffffffu, acc, 1, 8);
            if ((tid & 7) == 0)
                y[(size_t)(t0 + tt) * DINNER + head * HD + ps * 32 + pl] = fmaf(Dh, xp, acc);
        }
        __syncthreads();
    }
}

// ---------------- gate (y * silu(z)) + RMSNorm over 2048 ----------------
__global__ void __launch_bounds__(256) gatenorm_kernel(
    const float* __restrict__ zx, const float* __restrict__ norm_w,
    float* __restrict__ y)
{
    const int t = blockIdx.x;
    const int tid = threadIdx.x;
    __shared__ float red[8];

    float vals[8];
    float local = 0.f;
#pragma unroll
    for (int i = 0; i < 8; i++) {
        const int c = tid + i * 256;
        const float z  = zx[(size_t)t * DINPROJ + OFF_Z + c];
        const float yv = y[(size_t)t * DINNER + c];
        const float yg = yv * siluf(z);
        vals[i] = yg;
        local = fmaf(yg, yg, local);
    }
#pragma unroll
    for (int o = 16; o > 0; o >>= 1)
        local += __shfl_down_sync(0xffffffffu, local, o);
    if ((tid & 31) == 0) red[tid >> 5] = local;
    __syncthreads();
    if (tid < 8) {
        float v = red[tid];
#pragma unroll
        for (int o = 4; o > 0; o >>= 1)
            v += __shfl_down_sync(0xffu, v, o, 8);
        if (tid == 0) red[0] = v;
    }
    __syncthreads();
    const float scale = rsqrtf(red[0] * (1.f / (float)DINNER) + EPSF);
#pragma unroll
    for (int i = 0; i < 8; i++) {
        const int c = tid + i * 256;
        y[(size_t)t * DINNER + c] = vals[i] * scale * norm_w[c];
    }
}

// ---------------- launch ----------------
extern "C" void kernel_launch(void* const* d_in, const int* in_sizes, int n_in,
                              void* d_out, int out_size)
{
    const float* u        = (const float*)d_in[0];
    const float* W_in_f   = (const float*)d_in[1];
    const float* W_in_b   = (const float*)d_in[2];
    const float* conv_w_f = (const float*)d_in[3];
    const float* conv_b_f = (const float*)d_in[4];
    const float* conv_w_b = (const float*)d_in[5];
    const float* conv_b_b = (const float*)d_in[6];
    const float* dtb_f    = (const float*)d_in[7];
    const float* dtb_b    = (const float*)d_in[8];
    const float* Alog_f   = (const float*)d_in[9];
    const float* Alog_b   = (const float*)d_in[10];
    const float* D_f      = (const float*)d_in[11];
    const float* D_b      = (const float*)d_in[12];
    const float* nw_f     = (const float*)d_in[13];
    const float* nw_b     = (const float*)d_in[14];
    const float* W_out_f  = (const float*)d_in[15];
    const float* W_out_b  = (const float*)d_in[16];
    const float* W_out    = (const float*)d_in[17];
    float* out = (float*)d_out;

    float *zx_f, *zx_b, *xbc_f, *xbc_b, *dt_f, *dt_b, *dA_f, *dA_b, *y_f, *y_b, *o_f, *o_b;
    cudaGetSymbolAddress((void**)&zx_f,  g_zx_f);
    cudaGetSymbolAddress((void**)&zx_b,  g_zx_b);
    cudaGetSymbolAddress((void**)&xbc_f, g_xbc_f);
    cudaGetSymbolAddress((void**)&xbc_b, g_xbc_b);
    cudaGetSymbolAddress((void**)&dt_f,  g_dt_f);
    cudaGetSymbolAddress((void**)&dt_b,  g_dt_b);
    cudaGetSymbolAddress((void**)&dA_f,  g_dA_f);
    cudaGetSymbolAddress((void**)&dA_b,  g_dA_b);
    cudaGetSymbolAddress((void**)&y_f,   g_y_f);
    cudaGetSymbolAddress((void**)&y_b,   g_y_b);
    cudaGetSymbolAddress((void**)&o_f,   g_o_f);
    cudaGetSymbolAddress((void**)&o_b,   g_o_b);

    // 1) in_proj GEMMs: [1024,1024] x [4256,1024]^T
    {
        dim3 grid((DINPROJ + 127) / 128, L / 128);
        sgemm_nt<0><<<grid, 256>>>(u, nullptr, W_in_f, zx_f, L, DINPROJ, DMODEL);
        sgemm_nt<1><<<grid, 256>>>(u, nullptr, W_in_b, zx_b, L, DINPROJ, DMODEL);
    }
    // 2) conv + silu
    {
        const int n = L * CONVDIM;
        conv_silu_kernel<<<(n + 255) / 256, 256>>>(zx_f, conv_w_f, conv_b_f, xbc_f);
        conv_silu_kernel<<<(n + 255) / 256, 256>>>(zx_b, conv_w_b, conv_b_b, xbc_b);
    }
    // 3) dt / dA
    {
        const int n = L * NH;
        dt_kernel<<<(n + 255) / 256, 256>>>(zx_f, dtb_f, Alog_f, dt_f, dA_f);
        dt_kernel<<<(n + 255) / 256, 256>>>(zx_b, dtb_b, Alog_b, dt_b, dA_b);
    }
    // 4) scan
    {
        dim3 grid(2, NH);
        scan_kernel<<<grid, 256>>>(xbc_f, dt_f, dA_f, D_f, y_f);
        scan_kernel<<<grid, 256>>>(xbc_b, dt_b, dA_b, D_b, y_b);
    }
    // 5) gate + rmsnorm (in place on y)
    {
        gatenorm_kernel<<<L, 256>>>(zx_f, nw_f, y_f);
        gatenorm_kernel<<<L, 256>>>(zx_b, nw_b, y_b);
    }
    // 6) out_proj GEMMs: [1024,2048] x [1024,2048]^T
    {
        dim3 grid(DMODEL / 128, L / 128);
        sgemm_nt<0><<<grid, 256>>>(y_f, nullptr, W_out_f, o_f, L, DMODEL, DINNER);
        sgemm_nt<0><<<grid, 256>>>(y_b, nullptr, W_out_b, o_b, L, DMODEL, DINNER);
    }
    // 7) final: silu(concat(o_f, flip(o_b))) @ W_out^T
    {
        dim3 grid(DMODEL / 128, L / 128);
        sgemm_nt<2><<<grid, 256>>>(o_f, o_b, W_out, out, L, DMODEL, 2 * DMODEL);
    }
}

// round 3
// speedup vs baseline: 2.4730x; 2.4730x over previous
#include <cuda_runtime.h>
#include <cuda_bf16.h>
#include <math.h>
#include <stdint.h>

// ---------------- problem constants ----------------
#define L        1024
#define DMODEL   1024
#define DINNER   2048
#define NH       32
#define HD       64
#define CONVDIM  2176           // DINNER + 2*G*N
#define DINPROJ  4256           // 2*DINNER + 2*G*N + NH
#define DINPROJ_PAD 4352        // 34 * 128
#define OFF_Z    0
#define OFF_XBC  2048
#define OFF_B    2048
#define OFF_DT   4224
#define EPSF     1e-5f

// ---------------- scratch (device globals; no allocs allowed) ----------------
__device__ float g_zx_f[L * DINPROJ];
__device__ float g_zx_b[L * DINPROJ];
__device__ float g_xbc_f[L * CONVDIM];
__device__ float g_xbc_b[L * CONVDIM];
__device__ float g_dt_f[L * NH];
__device__ float g_dt_b[L * NH];
__device__ float g_dA_f[L * NH];
__device__ float g_dA_b[L * NH];
__device__ float g_o_f[L * DMODEL];
__device__ float g_o_b[L * DMODEL];
__device__ float g_y_f[L * DINNER];
__device__ float g_y_b[L * DINNER];

// bf16 hi/lo split weights
__device__ __nv_bfloat16 g_winf_hi[DINPROJ_PAD * DMODEL];
__device__ __nv_bfloat16 g_winf_lo[DINPROJ_PAD * DMODEL];
__device__ __nv_bfloat16 g_winb_hi[DINPROJ_PAD * DMODEL];
__device__ __nv_bfloat16 g_winb_lo[DINPROJ_PAD * DMODEL];
__device__ __nv_bfloat16 g_woutf_hi[DMODEL * DINNER];
__device__ __nv_bfloat16 g_woutf_lo[DMODEL * DINNER];
__device__ __nv_bfloat16 g_woutb_hi[DMODEL * DINNER];
__device__ __nv_bfloat16 g_woutb_lo[DMODEL * DINNER];
__device__ __nv_bfloat16 g_wfin_hi[DMODEL * (2 * DMODEL)];
__device__ __nv_bfloat16 g_wfin_lo[DMODEL * (2 * DMODEL)];

// bf16 hi/lo split activations
__device__ __nv_bfloat16 g_uhi[L * DMODEL];
__device__ __nv_bfloat16 g_ulo[L * DMODEL];
__device__ __nv_bfloat16 g_yhi_f[L * DINNER];
__device__ __nv_bfloat16 g_ylo_f[L * DINNER];
__device__ __nv_bfloat16 g_yhi_b[L * DINNER];
__device__ __nv_bfloat16 g_ylo_b[L * DINNER];
__device__ __nv_bfloat16 g_fhi[L * (2 * DMODEL)];
__device__ __nv_bfloat16 g_flo[L * (2 * DMODEL)];

__device__ __forceinline__ float siluf(float x) { return x / (1.f + expf(-x)); }

// ---------------- PTX helpers ----------------
__device__ __forceinline__ uint32_t smem_u32(const void* p) {
    uint32_t a;
    asm("{ .reg .u64 t; cvta.to.shared.u64 t, %1; cvt.u32.u64 %0, t; }" : "=r"(a) : "l"(p));
    return a;
}
__device__ __forceinline__ void cpa16(uint32_t dst, const void* src) {
    asm volatile("cp.async.cg.shared.global [%0], [%1], 16;" :: "r"(dst), "l"(src));
}
#define CP_COMMIT asm volatile("cp.async.commit_group;" ::: "memory")
#define CP_WAIT(n) asm volatile("cp.async.wait_group %0;" :: "n"(n) : "memory")

__device__ __forceinline__ void ldm_x4(uint32_t a[4], uint32_t addr) {
    asm volatile("ldmatrix.sync.aligned.m8n8.x4.shared.b16 {%0,%1,%2,%3}, [%4];"
        : "=r"(a[0]), "=r"(a[1]), "=r"(a[2]), "=r"(a[3]) : "r"(addr));
}
__device__ __forceinline__ void mma_bf16(float c[4], const uint32_t a[4], uint32_t b0, uint32_t b1) {
    asm volatile("mma.sync.aligned.m16n8k16.row.col.f32.bf16.bf16.f32 "
        "{%0,%1,%2,%3}, {%4,%5,%6,%7}, {%8,%9}, {%0,%1,%2,%3};"
        : "+f"(c[0]), "+f"(c[1]), "+f"(c[2]), "+f"(c[3])
        : "r"(a[0]), "r"(a[1]), "r"(a[2]), "r"(a[3]), "r"(b0), "r"(b1));
}
__device__ __forceinline__ uint32_t pack_bf2(__nv_bfloat16 a, __nv_bfloat16 b) {
    __nv_bfloat162 t(a, b);
    return *reinterpret_cast<uint32_t*>(&t);
}

// ---------------- HMMA GEMM: C[1024,N] = A[1024,K] * W[N,K]^T ----------------
// A,W given as bf16 hi/lo pairs; result = Ahi*Whi + Ahi*Wlo + Alo*Whi (fp32 acc).
// FLIP: write output row m to row 1023-m (time reversal folded into epilogue).
// Smem per stage: Ahi[128x32] @0, Alo @8192, Whi[BNx32] @16384, Wlo @16384+BN*64.
// Layout: 64B rows, 16B chunks XOR-swizzled: chunk' = chunk ^ ((row>>1)&3).
template <int BN, bool FLIP>
__global__ void __launch_bounds__(256, 2) hmma_gemm(
    const __nv_bfloat16* __restrict__ Ahi, const __nv_bfloat16* __restrict__ Alo,
    const __nv_bfloat16* __restrict__ Whi, const __nv_bfloat16* __restrict__ Wlo,
    float* __restrict__ C, int N, int K)
{
    constexpr int STAGE = 16384 + BN * 128;
    constexpr int MT = (BN == 128) ? 4 : 2;
    extern __shared__ __align__(128) char smem[];
    const uint32_t sb = smem_u32(smem);
    const int tid = threadIdx.x;
    const int lane = tid & 31;
    const int wid = tid >> 5;
    const int bm = blockIdx.y * 128;
    const int bn = blockIdx.x * BN;
    const int m0w = (BN == 128) ? (wid >> 2) * 64 : (wid >> 1) * 32;
    const int n0w = (BN == 128) ? (wid & 3) * 32 : (wid & 1) * 32;

    float acc[MT][4][4];
#pragma unroll
    for (int i = 0; i < MT; i++)
#pragma unroll
        for (int j = 0; j < 4; j++)
#pragma unroll
            for (int q = 0; q < 4; q++) acc[i][j][q] = 0.f;

    auto load_stage = [&](int s, int k0) {
        const uint32_t base = sb + s * STAGE;
#pragma unroll
        for (int it = 0; it < 2; it++) {
            const int q = tid + it * 256;
            const int r = q >> 2, c = q & 3;
            const uint32_t sw = r * 64 + ((uint32_t)(c ^ ((r >> 1) & 3)) << 4);
            const size_t go = (size_t)(bm + r) * K + k0 + c * 8;
            cpa16(base + sw, Ahi + go);
            cpa16(base + 8192 + sw, Alo + go);
        }
#pragma unroll
        for (int it = 0; it < BN / 64; it++) {
            const int q = tid + it * 256;
            const int r = q >> 2, c = q & 3;
            const uint32_t sw = r * 64 + ((uint32_t)(c ^ ((r >> 1) & 3)) << 4);
            const size_t go = (size_t)(bn + r) * K + k0 + c * 8;
            cpa16(base + 16384 + sw, Whi + go);
            cpa16(base + 16384 + BN * 64 + sw, Wlo + go);
        }
    };

    const int NC = K >> 5;
    load_stage(0, 0);
    CP_COMMIT;
    for (int i = 0; i < NC; i++) {
        if (i + 1 < NC) { load_stage((i + 1) & 1, (i + 1) << 5); CP_COMMIT; CP_WAIT(1); }
        else            { CP_WAIT(0); }
        __syncthreads();
        const uint32_t base = sb + (i & 1) * STAGE;
#pragma unroll
        for (int ks = 0; ks < 2; ks++) {
            const int c0 = ks * 2;
            uint32_t af[MT][4], bh[2][4], bl[2][4];
            // Ahi fragments
#pragma unroll
            for (int ii = 0; ii < MT; ii++) {
                const int row = m0w + ii * 16 + (lane & 15);
                const int ch = c0 + (lane >> 4);
                ldm_x4(af[ii], base + row * 64 + (uint32_t)((ch ^ ((row >> 1) & 3)) << 4));
            }
            // Whi fragments (2 x ldmatrix.x4 cover 4 n8 tiles)
#pragma unroll
            for (int j = 0; j < 2; j++) {
                const int row = n0w + j * 16 + ((lane >> 4) << 3) + (lane & 7);
                const int ch = c0 + ((lane >> 3) & 1);
                ldm_x4(bh[j], base + 16384 + row * 64 + (uint32_t)((ch ^ ((row >> 1) & 3)) << 4));
            }
            // T1: Ahi * Whi
#pragma unroll
            for (int ii = 0; ii < MT; ii++)
#pragma unroll
                for (int jj = 0; jj < 4; jj++)
                    mma_bf16(acc[ii][jj], af[ii], bh[jj >> 1][(jj & 1) * 2], bh[jj >> 1][(jj & 1) * 2 + 1]);
            // Wlo fragments
#pragma unroll
            for (int j = 0; j < 2; j++) {
                const int row = n0w + j * 16 + ((lane >> 4) << 3) + (lane & 7);
                const int ch = c0 + ((lane >> 3) & 1);
                ldm_x4(bl[j], base + 16384 + BN * 64 + row * 64 + (uint32_t)((ch ^ ((row >> 1) & 3)) << 4));
            }
            // T2: Ahi * Wlo
#pragma unroll
            for (int ii = 0; ii < MT; ii++)
#pragma unroll
                for (int jj = 0; jj < 4; jj++)
                    mma_bf16(acc[ii][jj], af[ii], bl[jj >> 1][(jj & 1) * 2], bl[jj >> 1][(jj & 1) * 2 + 1]);
            // Alo fragments (reuse af)
#pragma unroll
            for (int ii = 0; ii < MT; ii++) {
                const int row = m0w + ii * 16 + (lane & 15);
                const int ch = c0 + (lane >> 4);
                ldm_x4(af[ii], base + 8192 + row * 64 + (uint32_t)((ch ^ ((row >> 1) & 3)) << 4));
            }
            // T3: Alo * Whi
#pragma unroll
            for (int ii = 0; ii < MT; ii++)
#pragma unroll
                for (int jj = 0; jj < 4; jj++)
                    mma_bf16(acc[ii][jj], af[ii], bh[jj >> 1][(jj & 1) * 2], bh[jj >> 1][(jj & 1) * 2 + 1]);
        }
        __syncthreads();
    }

    // ---- epilogue: direct register -> gmem, float2 stores ----
#pragma unroll
    for (int ii = 0; ii < MT; ii++) {
        const int gr = bm + m0w + ii * 16 + (lane >> 2);
        const int r0 = FLIP ? (1023 - gr) : gr;
        const int r1 = FLIP ? (1023 - (gr + 8)) : (gr + 8);
#pragma unroll
        for (int jj = 0; jj < 4; jj++) {
            const int gc = bn + n0w + jj * 8 + (lane & 3) * 2;
            if (gc < N) {
                *reinterpret_cast<float2*>(&C[(size_t)r0 * N + gc]) = make_float2(acc[ii][jj][0], acc[ii][jj][1]);
                *reinterpret_cast<float2*>(&C[(size_t)r1 * N + gc]) = make_float2(acc[ii][jj][2], acc[ii][jj][3]);
            }
        }
    }
}

// ---------------- W hi/lo split (+ zero pad rows) ----------------
__global__ void w_split_kernel(const float* __restrict__ W,
                               __nv_bfloat16* __restrict__ hi, __nv_bfloat16* __restrict__ lo,
                               int rows, int K)
{
    const int r = blockIdx.y;
    const int c = (blockIdx.x * 256 + threadIdx.x) * 4;
    if (c >= K) return;
    float4 v = make_float4(0.f, 0.f, 0.f, 0.f);
    if (r < rows) v = *reinterpret_cast<const float4*>(&W[(size_t)r * K + c]);
    __nv_bfloat16 hx = __float2bfloat16(v.x), hy = __float2bfloat16(v.y),
                  hz = __float2bfloat16(v.z), hw = __float2bfloat16(v.w);
    __nv_bfloat16 lx = __float2bfloat16(v.x - __bfloat162float(hx));
    __nv_bfloat16 ly = __float2bfloat16(v.y - __bfloat162float(hy));
    __nv_bfloat16 lz = __float2bfloat16(v.z - __bfloat162float(hz));
    __nv_bfloat16 lw = __float2bfloat16(v.w - __bfloat162float(hw));
    *reinterpret_cast<uint2*>(&hi[(size_t)r * K + c]) = make_uint2(pack_bf2(hx, hy), pack_bf2(hz, hw));
    *reinterpret_cast<uint2*>(&lo[(size_t)r * K + c]) = make_uint2(pack_bf2(lx, ly), pack_bf2(lz, lw));
}

// ---------------- u -> hi/lo split ----------------
__global__ void u_split_kernel(const float* __restrict__ u,
                               __nv_bfloat16* __restrict__ hi, __nv_bfloat16* __restrict__ lo)
{
    const int i = (blockIdx.x * 256 + threadIdx.x) * 4;
    float4 v = *reinterpret_cast<const float4*>(&u[i]);
    __nv_bfloat16 hx = __float2bfloat16(v.x), hy = __float2bfloat16(v.y),
                  hz = __float2bfloat16(v.z), hw = __float2bfloat16(v.w);
    __nv_bfloat16 lx = __float2bfloat16(v.x - __bfloat162float(hx));
    __nv_bfloat16 ly = __float2bfloat16(v.y - __bfloat162float(hy));
    __nv_bfloat16 lz = __float2bfloat16(v.z - __bfloat162float(hz));
    __nv_bfloat16 lw = __float2bfloat16(v.w - __bfloat162float(hw));
    *reinterpret_cast<uint2*>(&hi[i]) = make_uint2(pack_bf2(hx, hy), pack_bf2(hz, hw));
    *reinterpret_cast<uint2*>(&lo[i]) = make_uint2(pack_bf2(lx, ly), pack_bf2(lz, lw));
}

// ---------------- final operand: silu(concat(o_f[m], o_b[1023-m])) -> hi/lo ----------------
__global__ void fin_split_kernel(const float* __restrict__ of, const float* __restrict__ ob,
                                 __nv_bfloat16* __restrict__ hi, __nv_bfloat16* __restrict__ lo)
{
    const int m = blockIdx.y;
    const int k = (blockIdx.x * 256 + threadIdx.x) * 4;
    float4 v;
    if (k < DMODEL) v = *reinterpret_cast<const float4*>(&of[(size_t)m * DMODEL + k]);
    else            v = *reinterpret_cast<const float4*>(&ob[(size_t)(1023 - m) * DMODEL + (k - DMODEL)]);
    v.x = siluf(v.x); v.y = siluf(v.y); v.z = siluf(v.z); v.w = siluf(v.w);
    __nv_bfloat16 hx = __float2bfloat16(v.x), hy = __float2bfloat16(v.y),
                  hz = __float2bfloat16(v.z), hw = __float2bfloat16(v.w);
    __nv_bfloat16 lx = __float2bfloat16(v.x - __bfloat162float(hx));
    __nv_bfloat16 ly = __float2bfloat16(v.y - __bfloat162float(hy));
    __nv_bfloat16 lz = __float2bfloat16(v.z - __bfloat162float(hz));
    __nv_bfloat16 lw = __float2bfloat16(v.w - __bfloat162float(hw));
    *reinterpret_cast<uint2*>(&hi[(size_t)m * (2 * DMODEL) + k]) = make_uint2(pack_bf2(hx, hy), pack_bf2(hz, hw));
    *reinterpret_cast<uint2*>(&lo[(size_t)m * (2 * DMODEL) + k]) = make_uint2(pack_bf2(lx, ly), pack_bf2(lz, lw));
}

// ---------------- depthwise causal conv (width 4) + SiLU ----------------
__global__ void conv_silu_kernel(const float* __restrict__ zx,
                                 const float* __restrict__ cw,
                                 const float* __restrict__ cb,
                                 float* __restrict__ out)
{
    const int idx = blockIdx.x * blockDim.x + threadIdx.x;
    if (idx >= L * CONVDIM) return;
    const int t = idx / CONVDIM;
    const int c = idx - t * CONVDIM;
    float acc = cb[c];
#pragma unroll
    for (int k = 0; k < 4; k++) {
        const int tt = t - 3 + k;
        if (tt >= 0)
            acc = fmaf(zx[(size_t)tt * DINPROJ + OFF_XBC + c], cw[c * 4 + k], acc);
    }
    out[(size_t)t * CONVDIM + c] = siluf(acc);
}

// ---------------- dt softplus + dA ----------------
__global__ void dt_kernel(const float* __restrict__ zx,
                          const float* __restrict__ dt_bias,
                          const float* __restrict__ A_log,
                          float* __restrict__ dt_out,
                          float* __restrict__ dA_out)
{
    const int idx = blockIdx.x * blockDim.x + threadIdx.x;
    if (idx >= L * NH) return;
    const int h = idx & (NH - 1);
    const float v = zx[(size_t)(idx >> 5) * DINPROJ + OFF_DT + h] + dt_bias[h];
    const float sp = (v > 20.f) ? v : log1pf(expf(v));
    dt_out[idx] = sp;
    dA_out[idx] = expf(sp * (-expf(A_log[h])));
}

// ---------------- SSM scan ----------------
#define SCHUNK 16
__global__ void __launch_bounds__(256) scan_kernel(
    const float* __restrict__ xbc, const float* __restrict__ dt,
    const float* __restrict__ dA, const float* __restrict__ Dp,
    float* __restrict__ y)
{
    const int head = blockIdx.y;
    const int ps   = blockIdx.x;
    const int tid  = threadIdx.x;
    const int pl   = tid >> 3;
    const int n0   = (tid & 7) * 8;
    const float Dh = Dp[head];
    const int xoff = head * HD + ps * 32;

    __shared__ float sB[SCHUNK][64];
    __shared__ float sC[SCHUNK][64];
    __shared__ float sx[SCHUNK][32];
    __shared__ float sdt[SCHUNK];
    __shared__ float sdA[SCHUNK];

    float h[8];
#pragma unroll
    for (int j = 0; j < 8; j++) h[j] = 0.f;

    for (int t0 = 0; t0 < L; t0 += SCHUNK) {
        {
            const int lt = tid >> 4;
            const int lc = (tid & 15) * 4;
            const int t  = t0 + lt;
            *reinterpret_cast<float4*>(&sB[lt][lc]) =
                *reinterpret_cast<const float4*>(&xbc[(size_t)t * CONVDIM + OFF_B + lc]);
            *reinterpret_cast<float4*>(&sC[lt][lc]) =
                *reinterpret_cast<const float4*>(&xbc[(size_t)t * CONVDIM + OFF_B + 64 + lc]);
            if (lc < 32)
                *reinterpret_cast<float4*>(&sx[lt][lc]) =
                    *reinterpret_cast<const float4*>(&xbc[(size_t)t * CONVDIM + xoff + lc]);
            if (tid < SCHUNK) {
                sdt[tid] = dt[(size_t)(t0 + tid) * NH + head];
                sdA[tid] = dA[(size_t)(t0 + tid) * NH + head];
            }
        }
        __syncthreads();

        for (int tt = 0; tt < SCHUNK; tt++) {
            const float dtv = sdt[tt];
            const float dAv = sdA[tt];
            const float xp  = sx[tt][pl];
            const float dtx = dtv * xp;
            float b[8], c[8];
            *reinterpret_cast<float4*>(b)     = *reinterpret_cast<const float4*>(&sB[tt][n0]);
            *reinterpret_cast<float4*>(b + 4) = *reinterpret_cast<const float4*>(&sB[tt][n0 + 4]);
            *reinterpret_cast<float4*>(c)     = *reinterpret_cast<const float4*>(&sC[tt][n0]);
            *reinterpret_cast<float4*>(c + 4) = *reinterpret_cast<const float4*>(&sC[tt][n0 + 4]);
            float acc = 0.f;
#pragma unroll
            for (int j = 0; j < 8; j++) {
                h[j] = fmaf(h[j], dAv, dtx * b[j]);
                acc  = fmaf(h[j], c[j], acc);
            }
            acc += __shfl_down_sync(0xffffffffu, acc, 4, 8);
            acc += __shfl_down_sync(0xffffffffu, acc, 2, 8);
            acc += __shfl_down_sync(0xffffffffu, acc, 1, 8);
            if ((tid & 7) == 0)
                y[(size_t)(t0 + tt) * DINNER + head * HD + ps * 32 + pl] = fmaf(Dh, xp, acc);
        }
        __syncthreads();
    }
}

// ---------------- gate (y * silu(z)) + RMSNorm -> bf16 hi/lo split ----------------
__global__ void __launch_bounds__(256) gatenorm_kernel(
    const float* __restrict__ zx, const float* __restrict__ norm_w,
    const float* __restrict__ y,
    __nv_bfloat16* __restrict__ yhi, __nv_bfloat16* __restrict__ ylo)
{
    const int t = blockIdx.x;
    const int tid = threadIdx.x;
    __shared__ float red[8];

    float vals[8];
    float local = 0.f;
#pragma unroll
    for (int i = 0; i < 8; i++) {
        const int c = tid + i * 256;
        const float z  = zx[(size_t)t * DINPROJ + OFF_Z + c];
        const float yv = y[(size_t)t * DINNER + c];
        const float yg = yv * siluf(z);
        vals[i] = yg;
        local = fmaf(yg, yg, local);
    }
#pragma unroll
    for (int o = 16; o > 0; o >>= 1)
        local += __shfl_down_sync(0xffffffffu, local, o);
    if ((tid & 31) == 0) red[tid >> 5] = local;
    __syncthreads();
    if (tid < 8) {
        float v = red[tid];
#pragma unroll
        for (int o = 4; o > 0; o >>= 1)
            v += __shfl_down_sync(0xffu, v, o, 8);
        if (tid == 0) red[0] = v;
    }
    __syncthreads();
    const float scale = rsqrtf(red[0] * (1.f / (float)DINNER) + EPSF);
#pragma unroll
    for (int i = 0; i < 8; i++) {
        const int c = tid + i * 256;
        const float v = vals[i] * scale * norm_w[c];
        const __nv_bfloat16 h = __float2bfloat16(v);
        yhi[(size_t)t * DINNER + c] = h;
        ylo[(size_t)t * DINNER + c] = __float2bfloat16(v - __bfloat162float(h));
    }
}

// ---------------- launch ----------------
extern "C" void kernel_launch(void* const* d_in, const int* in_sizes, int n_in,
                              void* d_out, int out_size)
{
    const float* u        = (const float*)d_in[0];
    const float* W_in_f   = (const float*)d_in[1];
    const float* W_in_b   = (const float*)d_in[2];
    const float* conv_w_f = (const float*)d_in[3];
    const float* conv_b_f = (const float*)d_in[4];
    const float* conv_w_b = (const float*)d_in[5];
    const float* conv_b_b = (const float*)d_in[6];
    const float* dtb_f    = (const float*)d_in[7];
    const float* dtb_b    = (const float*)d_in[8];
    const float* Alog_f   = (const float*)d_in[9];
    const float* Alog_b   = (const float*)d_in[10];
    const float* D_f      = (const float*)d_in[11];
    const float* D_b      = (const float*)d_in[12];
    const float* nw_f     = (const float*)d_in[13];
    const float* nw_b     = (const float*)d_in[14];
    const float* W_out_f  = (const float*)d_in[15];
    const float* W_out_b  = (const float*)d_in[16];
    const float* W_out    = (const float*)d_in[17];
    float* out = (float*)d_out;

    float *zx_f, *zx_b, *xbc_f, *xbc_b, *dt_f, *dt_b, *dA_f, *dA_b, *y_f, *y_b, *o_f, *o_b;
    cudaGetSymbolAddress((void**)&zx_f,  g_zx_f);
    cudaGetSymbolAddress((void**)&zx_b,  g_zx_b);
    cudaGetSymbolAddress((void**)&xbc_f, g_xbc_f);
    cudaGetSymbolAddress((void**)&xbc_b, g_xbc_b);
    cudaGetSymbolAddress((void**)&dt_f,  g_dt_f);
    cudaGetSymbolAddress((void**)&dt_b,  g_dt_b);
    cudaGetSymbolAddress((void**)&dA_f,  g_dA_f);
    cudaGetSymbolAddress((void**)&dA_b,  g_dA_b);
    cudaGetSymbolAddress((void**)&y_f,   g_y_f);
    cudaGetSymbolAddress((void**)&y_b,   g_y_b);
    cudaGetSymbolAddress((void**)&o_f,   g_o_f);
    cudaGetSymbolAddress((void**)&o_b,   g_o_b);

    __nv_bfloat16 *winf_hi, *winf_lo, *winb_hi, *winb_lo;
    __nv_bfloat16 *woutf_hi, *woutf_lo, *woutb_hi, *woutb_lo, *wfin_hi, *wfin_lo;
    __nv_bfloat16 *uhi, *ulo, *yhi_f, *ylo_f, *yhi_b, *ylo_b, *fhi, *flo;
    cudaGetSymbolAddress((void**)&winf_hi,  g_winf_hi);
    cudaGetSymbolAddress((void**)&winf_lo,  g_winf_lo);
    cudaGetSymbolAddress((void**)&winb_hi,  g_winb_hi);
    cudaGetSymbolAddress((void**)&winb_lo,  g_winb_lo);
    cudaGetSymbolAddress((void**)&woutf_hi, g_woutf_hi);
    cudaGetSymbolAddress((void**)&woutf_lo, g_woutf_lo);
    cudaGetSymbolAddress((void**)&woutb_hi, g_woutb_hi);
    cudaGetSymbolAddress((void**)&woutb_lo, g_woutb_lo);
    cudaGetSymbolAddress((void**)&wfin_hi,  g_wfin_hi);
    cudaGetSymbolAddress((void**)&wfin_lo,  g_wfin_lo);
    cudaGetSymbolAddress((void**)&uhi,   g_uhi);
    cudaGetSymbolAddress((void**)&ulo,   g_ulo);
    cudaGetSymbolAddress((void**)&yhi_f, g_yhi_f);
    cudaGetSymbolAddress((void**)&ylo_f, g_ylo_f);
    cudaGetSymbolAddress((void**)&yhi_b, g_yhi_b);
    cudaGetSymbolAddress((void**)&ylo_b, g_ylo_b);
    cudaGetSymbolAddress((void**)&fhi,   g_fhi);
    cudaGetSymbolAddress((void**)&flo,   g_flo);

    cudaFuncSetAttribute(hmma_gemm<128, false>, cudaFuncAttributeMaxDynamicSharedMemorySize, 2 * (16384 + 128 * 128));
    cudaFuncSetAttribute(hmma_gemm<128, true>,  cudaFuncAttributeMaxDynamicSharedMemorySize, 2 * (16384 + 128 * 128));
    cudaFuncSetAttribute(hmma_gemm<64, false>,  cudaFuncAttributeMaxDynamicSharedMemorySize, 2 * (16384 + 64 * 128));

    // 0) weight + input splits
    w_split_kernel<<<dim3(1, DINPROJ_PAD), 256>>>(W_in_f, winf_hi, winf_lo, DINPROJ, DMODEL);
    w_split_kernel<<<dim3(1, DINPROJ_PAD), 256>>>(W_in_b, winb_hi, winb_lo, DINPROJ, DMODEL);
    w_split_kernel<<<dim3(2, DMODEL), 256>>>(W_out_f, woutf_hi, woutf_lo, DMODEL, DINNER);
    w_split_kernel<<<dim3(2, DMODEL), 256>>>(W_out_b, woutb_hi, woutb_lo, DMODEL, DINNER);
    w_split_kernel<<<dim3(2, DMODEL), 256>>>(W_out, wfin_hi, wfin_lo, DMODEL, 2 * DMODEL);
    u_split_kernel<<<L * DMODEL / 1024, 256>>>(u, uhi, ulo);

    // 1) in_proj GEMMs (dir-b output rows flipped == time-reversed input)
    {
        dim3 grid(DINPROJ_PAD / 128, 8);
        hmma_gemm<128, false><<<grid, 256, 2 * (16384 + 128 * 128)>>>(uhi, ulo, winf_hi, winf_lo, zx_f, DINPROJ, DMODEL);
        hmma_gemm<128, true><<<grid, 256, 2 * (16384 + 128 * 128)>>>(uhi, ulo, winb_hi, winb_lo, zx_b, DINPROJ, DMODEL);
    }
    // 2) conv + silu
    {
        const int n = L * CONVDIM;
        conv_silu_kernel<<<(n + 255) / 256, 256>>>(zx_f, conv_w_f, conv_b_f, xbc_f);
        conv_silu_kernel<<<(n + 255) / 256, 256>>>(zx_b, conv_w_b, conv_b_b, xbc_b);
    }
    // 3) dt / dA
    {
        const int n = L * NH;
        dt_kernel<<<(n + 255) / 256, 256>>>(zx_f, dtb_f, Alog_f, dt_f, dA_f);
        dt_kernel<<<(n + 255) / 256, 256>>>(zx_b, dtb_b, Alog_b, dt_b, dA_b);
    }
    // 4) scan
    {
        dim3 grid(2, NH);
        scan_kernel<<<grid, 256>>>(xbc_f, dt_f, dA_f, D_f, y_f);
        scan_kernel<<<grid, 256>>>(xbc_b, dt_b, dA_b, D_b, y_b);
    }
    // 5) gate + rmsnorm -> bf16 split
    {
        gatenorm_kernel<<<L, 256>>>(zx_f, nw_f, y_f, yhi_f, ylo_f);
        gatenorm_kernel<<<L, 256>>>(zx_b, nw_b, y_b, yhi_b, ylo_b);
    }
    // 6) out_proj GEMMs
    {
        dim3 grid(DMODEL / 64, 8);
        hmma_gemm<64, false><<<grid, 256, 2 * (16384 + 64 * 128)>>>(yhi_f, ylo_f, woutf_hi, woutf_lo, o_f, DMODEL, DINNER);
        hmma_gemm<64, false><<<grid, 256, 2 * (16384 + 64 * 128)>>>(yhi_b, ylo_b, woutb_hi, woutb_lo, o_b, DMODEL, DINNER);
    }
    // 7) final: silu(concat(o_f, flip(o_b))) @ W_out^T
    {
        fin_split_kernel<<<dim3(2 * DMODEL / 1024, L), 256>>>(o_f, o_b, fhi, flo);
        dim3 grid(DMODEL / 64, 8);
        hmma_gemm<64, false><<<grid, 256, 2 * (16384 + 64 * 128)>>>(fhi, flo, wfin_hi, wfin_lo, out, DMODEL, 2 * DMODEL);
    }
}